// round 1
// baseline (speedup 1.0000x reference)
#include <cuda_runtime.h>
#include <cstdint>
#include <cfloat>

// Problem dimensions (fixed by the dataset)
#define B_  16384      // batch
#define TD_ 4096       // T*D input dim
#define L_  1024       // latent dim
#define K_  8192       // codebook size
#define O_  128        // output dim

// ---------------- scratch (device globals; no allocations allowed) ----------
__device__ float  g_ze[(size_t)B_ * L_];   // 64 MB  z_e
__device__ float  g_zq[(size_t)B_ * L_];   // 64 MB  z_q (straight-through forward)
__device__ float  g_P[B_];                 // ||z_e||^2 per row
__device__ float  g_c[K_];                 // ||e_k||^2 per codebook row
__device__ int    g_idx[B_];               // argmin indices
__device__ double g_rowloss[B_];           // per-row loss partials (deterministic)

// ---------------- row sum-of-squares: one warp per row ----------------------
__global__ void rowsumsq_kernel(const float* __restrict__ src, float* __restrict__ dst,
                                int rows, int cols)
{
    int row  = blockIdx.x * (blockDim.x >> 5) + (threadIdx.x >> 5);
    int lane = threadIdx.x & 31;
    if (row >= rows) return;
    const float* r = src + (size_t)row * cols;
    double s = 0.0;
    for (int j = lane; j < cols; j += 32) {
        float v = r[j];
        s += (double)v * (double)v;
    }
    #pragma unroll
    for (int o = 16; o > 0; o >>= 1)
        s += __shfl_down_sync(0xffffffffu, s, o);
    if (lane == 0) dst[row] = (float)s;
}

// ---------------- classic 128x128x8 register-tiled SGEMM (C = A*B^T + bias) -
// A: [M,K] row-major, B: [N,K] row-major, C: [M,N] row-major.
__global__ __launch_bounds__(256) void sgemm_nt_bias(
    const float* __restrict__ A, const float* __restrict__ Bm,
    const float* __restrict__ bias, float* __restrict__ C,
    int M, int N, int Kd)
{
    const int BM = 128, BN = 128, BK = 8;
    __shared__ float As[BK][BM];
    __shared__ float Bs[BK][BN];

    int bm = blockIdx.y * BM;
    int bn = blockIdx.x * BN;
    int tid = threadIdx.x;
    int tx = tid & 15, ty = tid >> 4;        // 16x16 thread grid, 8x8 micro-tile
    int lrow = tid >> 1;                     // 0..127
    int lcol = (tid & 1) * 4;                // 0 or 4

    const float* Aptr = A  + (size_t)(bm + lrow) * Kd + lcol;
    const float* Bptr = Bm + (size_t)(bn + lrow) * Kd + lcol;

    float acc[8][8];
    #pragma unroll
    for (int i = 0; i < 8; i++)
        #pragma unroll
        for (int j = 0; j < 8; j++) acc[i][j] = 0.0f;

    for (int k0 = 0; k0 < Kd; k0 += BK) {
        float4 av = *(const float4*)(Aptr + k0);
        float4 bv = *(const float4*)(Bptr + k0);
        As[lcol + 0][lrow] = av.x; As[lcol + 1][lrow] = av.y;
        As[lcol + 2][lrow] = av.z; As[lcol + 3][lrow] = av.w;
        Bs[lcol + 0][lrow] = bv.x; Bs[lcol + 1][lrow] = bv.y;
        Bs[lcol + 2][lrow] = bv.z; Bs[lcol + 3][lrow] = bv.w;
        __syncthreads();
        #pragma unroll
        for (int kk = 0; kk < BK; kk++) {
            float ar[8], br[8];
            #pragma unroll
            for (int i = 0; i < 8; i++) ar[i] = As[kk][ty * 8 + i];
            #pragma unroll
            for (int j = 0; j < 8; j++) br[j] = Bs[kk][tx * 8 + j];
            #pragma unroll
            for (int i = 0; i < 8; i++)
                #pragma unroll
                for (int j = 0; j < 8; j++)
                    acc[i][j] = fmaf(ar[i], br[j], acc[i][j]);
        }
        __syncthreads();
    }

    #pragma unroll
    for (int i = 0; i < 8; i++) {
        int r = bm + ty * 8 + i;
        #pragma unroll
        for (int j = 0; j < 8; j += 4) {
            int c = bn + tx * 8 + j;
            float4 o;
            o.x = acc[i][j + 0] + bias[c + 0];
            o.y = acc[i][j + 1] + bias[c + 1];
            o.z = acc[i][j + 2] + bias[c + 2];
            o.w = acc[i][j + 3] + bias[c + 3];
            *(float4*)&C[(size_t)r * N + c] = o;
        }
    }
}

// ---------------- fused z_e @ codebook^T -> quantized distance -> argmin ----
// Each block owns 128 rows and sweeps all K_=8192 codes (N never materialized).
// Epilogue reproduces the reference's fp32 rounding order:
//   t = fl(P - fl(2*dot));  d = fl(t + c);  argmin with first-index tie-break.
__global__ __launch_bounds__(256) void dist_argmin_kernel(
    const float* __restrict__ cb, float* __restrict__ out_idx_f, int write_idx)
{
    const int BM = 128, BN = 128, BK = 8;
    __shared__ float As[BK][BM];
    __shared__ float Bs[BK][BN];

    int bm = blockIdx.x * BM;
    int tid = threadIdx.x;
    int tx = tid & 15, ty = tid >> 4;
    int lrow = tid >> 1;
    int lcol = (tid & 1) * 4;

    float bestv[8];
    int   besti[8];
    float Prow[8];
    #pragma unroll
    for (int i = 0; i < 8; i++) {
        bestv[i] = FLT_MAX;
        besti[i] = 0;
        Prow[i]  = g_P[bm + ty * 8 + i];
    }

    const float* Aptr = g_ze + (size_t)(bm + lrow) * L_ + lcol;

    for (int n0 = 0; n0 < K_; n0 += BN) {
        const float* Bptr = cb + (size_t)(n0 + lrow) * L_ + lcol;
        float acc[8][8];
        #pragma unroll
        for (int i = 0; i < 8; i++)
            #pragma unroll
            for (int j = 0; j < 8; j++) acc[i][j] = 0.0f;

        for (int k0 = 0; k0 < L_; k0 += BK) {
            float4 av = *(const float4*)(Aptr + k0);
            float4 bv = *(const float4*)(Bptr + k0);
            As[lcol + 0][lrow] = av.x; As[lcol + 1][lrow] = av.y;
            As[lcol + 2][lrow] = av.z; As[lcol + 3][lrow] = av.w;
            Bs[lcol + 0][lrow] = bv.x; Bs[lcol + 1][lrow] = bv.y;
            Bs[lcol + 2][lrow] = bv.z; Bs[lcol + 3][lrow] = bv.w;
            __syncthreads();
            #pragma unroll
            for (int kk = 0; kk < BK; kk++) {
                float ar[8], br[8];
                #pragma unroll
                for (int i = 0; i < 8; i++) ar[i] = As[kk][ty * 8 + i];
                #pragma unroll
                for (int j = 0; j < 8; j++) br[j] = Bs[kk][tx * 8 + j];
                #pragma unroll
                for (int i = 0; i < 8; i++)
                    #pragma unroll
                    for (int j = 0; j < 8; j++)
                        acc[i][j] = fmaf(ar[i], br[j], acc[i][j]);
            }
            __syncthreads();
        }

        float cvals[8];
        #pragma unroll
        for (int j = 0; j < 8; j++) cvals[j] = __ldg(&g_c[n0 + tx * 8 + j]);

        #pragma unroll
        for (int i = 0; i < 8; i++) {
            #pragma unroll
            for (int j = 0; j < 8; j++) {
                float t = Prow[i] - 2.0f * acc[i][j];   // fl(P - fl(2*dot))
                float d = t + cvals[j];                  // fl(t + c)
                int col = n0 + tx * 8 + j;
                if (d < bestv[i]) { bestv[i] = d; besti[i] = col; }
            }
        }
    }

    // cross-thread per-row reduction with first-index tie-break
    __shared__ float sv[128][16];
    __shared__ int   si[128][16];
    #pragma unroll
    for (int i = 0; i < 8; i++) {
        sv[ty * 8 + i][tx] = bestv[i];
        si[ty * 8 + i][tx] = besti[i];
    }
    __syncthreads();
    if (tid < 128) {
        float bv = sv[tid][0];
        int   bi = si[tid][0];
        #pragma unroll
        for (int t = 1; t < 16; t++) {
            float v = sv[tid][t];
            int  ix = si[tid][t];
            if (v < bv || (v == bv && ix < bi)) { bv = v; bi = ix; }
        }
        g_idx[bm + tid] = bi;
        if (write_idx) out_idx_f[bm + tid] = (float)bi;
    }
}

// ---------------- per-row loss partial + z_q construction -------------------
__global__ void loss_zq_kernel(const float* __restrict__ cb)
{
    int row = blockIdx.x;
    const float* ze = g_ze + (size_t)row * L_;
    const float* q  = cb   + (size_t)g_idx[row] * L_;
    float* zq = g_zq + (size_t)row * L_;

    double s = 0.0;
    for (int j = threadIdx.x; j < L_; j += blockDim.x) {
        float z  = ze[j];
        float qq = q[j];
        float dlt = qq - z;            // fl(q - z)
        s += (double)dlt * (double)dlt;
        zq[j] = z + dlt;               // fl(z + fl(q - z))  (straight-through fwd)
    }
    __shared__ double sh[256];
    sh[threadIdx.x] = s;
    __syncthreads();
    for (int o = 128; o > 0; o >>= 1) {
        if (threadIdx.x < o) sh[threadIdx.x] += sh[threadIdx.x + o];
        __syncthreads();
    }
    if (threadIdx.x == 0) g_rowloss[row] = sh[0];
}

__global__ void loss_reduce_kernel(float* __restrict__ out_loss)
{
    __shared__ double sh[256];
    double s = 0.0;
    for (int r = threadIdx.x; r < B_; r += 256) s += g_rowloss[r];
    sh[threadIdx.x] = s;
    __syncthreads();
    for (int o = 128; o > 0; o >>= 1) {
        if (threadIdx.x < o) sh[threadIdx.x] += sh[threadIdx.x + o];
        __syncthreads();
    }
    if (threadIdx.x == 0) {
        float m = (float)(sh[0] / ((double)B_ * (double)L_));
        out_loss[0] = m + 0.25f * m;   // q_latent + 0.25 * e_latent (identical fwd)
    }
}

// ---------------- row softmax over O_=128 ------------------------------------
__global__ void softmax_kernel(float* __restrict__ logits)
{
    int row = blockIdx.x;
    float* p = logits + (size_t)row * O_;
    float v = p[threadIdx.x];

    __shared__ float shm[4];
    float m = v;
    #pragma unroll
    for (int o = 16; o > 0; o >>= 1) m = fmaxf(m, __shfl_xor_sync(0xffffffffu, m, o));
    if ((threadIdx.x & 31) == 0) shm[threadIdx.x >> 5] = m;
    __syncthreads();
    float mm = fmaxf(fmaxf(shm[0], shm[1]), fmaxf(shm[2], shm[3]));
    __syncthreads();

    float e = expf(v - mm);
    float s = e;
    #pragma unroll
    for (int o = 16; o > 0; o >>= 1) s += __shfl_xor_sync(0xffffffffu, s, o);
    if ((threadIdx.x & 31) == 0) shm[threadIdx.x >> 5] = s;
    __syncthreads();
    float ss = shm[0] + shm[1] + shm[2] + shm[3];
    p[threadIdx.x] = e / ss;
}

// ---------------- launch ------------------------------------------------------
extern "C" void kernel_launch(void* const* d_in, const int* in_sizes, int n_in,
                              void* d_out, int out_size)
{
    const float* x     = (const float*)d_in[0];
    const float* W_enc = (const float*)d_in[1];
    const float* b_enc = (const float*)d_in[2];
    const float* cb    = (const float*)d_in[3];
    const float* W_cls = (const float*)d_in[4];
    const float* b_cls = (const float*)d_in[5];
    float* out = (float*)d_out;

    float* out_logits = out;
    float* out_loss   = out + (size_t)B_ * O_;
    float* out_idx    = out + (size_t)B_ * O_ + 1;
    int has_loss = (out_size >= B_ * O_ + 1);
    int has_idx  = (out_size >= B_ * O_ + 1 + B_);

    void *p_ze, *p_zq;
    cudaGetSymbolAddress(&p_ze, g_ze);
    cudaGetSymbolAddress(&p_zq, g_zq);
    void *p_P, *p_c;
    cudaGetSymbolAddress(&p_P, g_P);
    cudaGetSymbolAddress(&p_c, g_c);
    float* ze = (float*)p_ze;
    float* zq = (float*)p_zq;
    float* Pv = (float*)p_P;
    float* cv = (float*)p_c;

    // 1) codebook row norms
    rowsumsq_kernel<<<K_ / 8, 256>>>(cb, cv, K_, L_);

    // 2) z_e = x @ W_enc^T + b_enc
    {
        dim3 grid(L_ / 128, B_ / 128);
        sgemm_nt_bias<<<grid, 256>>>(x, W_enc, b_enc, ze, B_, L_, TD_);
    }

    // 3) row norms of z_e
    rowsumsq_kernel<<<B_ / 8, 256>>>(ze, Pv, B_, L_);

    // 4) fused distance + argmin (codes never materialized)
    dist_argmin_kernel<<<B_ / 128, 256>>>(cb, out_idx, has_idx);

    // 5) per-row loss + z_q
    loss_zq_kernel<<<B_, 256>>>(cb);

    // 6) deterministic loss reduce -> vq_loss
    if (has_loss) loss_reduce_kernel<<<1, 256>>>(out_loss);

    // 7) pre-logits = z_q @ W_cls^T + b_cls
    {
        dim3 grid(O_ / 128, B_ / 128);
        sgemm_nt_bias<<<grid, 256>>>(zq, W_cls, b_cls, out_logits, B_, O_, L_);
    }

    // 8) row softmax
    softmax_kernel<<<B_, 128>>>(out_logits);
}

// round 2
// speedup vs baseline: 1.0007x; 1.0007x over previous
#include <cuda_runtime.h>
#include <cstdint>
#include <cfloat>

// Problem dimensions (fixed by the dataset)
#define B_  16384      // batch
#define TD_ 4096       // T*D input dim
#define L_  1024       // latent dim
#define K_  8192       // codebook size
#define O_  128        // output dim

// ---------------- scratch (device globals; no allocations allowed) ----------
__device__ float  g_ze[(size_t)B_ * L_];   // 64 MB  z_e
__device__ float  g_zq[(size_t)B_ * L_];   // 64 MB  z_q (straight-through forward)
__device__ float  g_P[B_];                 // ||z_e||^2 per row
__device__ float  g_c[K_];                 // ||e_k||^2 per codebook row
__device__ int    g_idx[B_];               // argmin indices
__device__ double g_rowloss[B_];           // per-row loss partials (deterministic)

// ---------------- row sum-of-squares: one warp per row ----------------------
__global__ void rowsumsq_kernel(const float* __restrict__ src, float* __restrict__ dst,
                                int rows, int cols)
{
    int row  = blockIdx.x * (blockDim.x >> 5) + (threadIdx.x >> 5);
    int lane = threadIdx.x & 31;
    if (row >= rows) return;
    const float* r = src + (size_t)row * cols;
    double s = 0.0;
    for (int j = lane; j < cols; j += 32) {
        float v = r[j];
        s += (double)v * (double)v;
    }
    #pragma unroll
    for (int o = 16; o > 0; o >>= 1)
        s += __shfl_down_sync(0xffffffffu, s, o);
    if (lane == 0) dst[row] = (float)s;
}

// ---------------- classic 128x128x8 register-tiled SGEMM (C = A*B^T + bias) -
// A: [M,K] row-major, B: [N,K] row-major, C: [M,N] row-major.
__global__ __launch_bounds__(256) void sgemm_nt_bias(
    const float* __restrict__ A, const float* __restrict__ Bm,
    const float* __restrict__ bias, float* __restrict__ C,
    int M, int N, int Kd)
{
    const int BM = 128, BN = 128, BK = 8;
    __shared__ float As[BK][BM];
    __shared__ float Bs[BK][BN];

    int bm = blockIdx.y * BM;
    int bn = blockIdx.x * BN;
    int tid = threadIdx.x;
    int tx = tid & 15, ty = tid >> 4;        // 16x16 thread grid, 8x8 micro-tile
    int lrow = tid >> 1;                     // 0..127
    int lcol = (tid & 1) * 4;                // 0 or 4

    const float* Aptr = A  + (size_t)(bm + lrow) * Kd + lcol;
    const float* Bptr = Bm + (size_t)(bn + lrow) * Kd + lcol;

    float acc[8][8];
    #pragma unroll
    for (int i = 0; i < 8; i++)
        #pragma unroll
        for (int j = 0; j < 8; j++) acc[i][j] = 0.0f;

    for (int k0 = 0; k0 < Kd; k0 += BK) {
        float4 av = *(const float4*)(Aptr + k0);
        float4 bv = *(const float4*)(Bptr + k0);
        As[lcol + 0][lrow] = av.x; As[lcol + 1][lrow] = av.y;
        As[lcol + 2][lrow] = av.z; As[lcol + 3][lrow] = av.w;
        Bs[lcol + 0][lrow] = bv.x; Bs[lcol + 1][lrow] = bv.y;
        Bs[lcol + 2][lrow] = bv.z; Bs[lcol + 3][lrow] = bv.w;
        __syncthreads();
        #pragma unroll
        for (int kk = 0; kk < BK; kk++) {
            float ar[8], br[8];
            #pragma unroll
            for (int i = 0; i < 8; i++) ar[i] = As[kk][ty * 8 + i];
            #pragma unroll
            for (int j = 0; j < 8; j++) br[j] = Bs[kk][tx * 8 + j];
            #pragma unroll
            for (int i = 0; i < 8; i++)
                #pragma unroll
                for (int j = 0; j < 8; j++)
                    acc[i][j] = fmaf(ar[i], br[j], acc[i][j]);
        }
        __syncthreads();
    }

    #pragma unroll
    for (int i = 0; i < 8; i++) {
        int r = bm + ty * 8 + i;
        #pragma unroll
        for (int j = 0; j < 8; j += 4) {
            int c = bn + tx * 8 + j;
            float4 o;
            o.x = acc[i][j + 0] + bias[c + 0];
            o.y = acc[i][j + 1] + bias[c + 1];
            o.z = acc[i][j + 2] + bias[c + 2];
            o.w = acc[i][j + 3] + bias[c + 3];
            *(float4*)&C[(size_t)r * N + c] = o;
        }
    }
}

// ---------------- fused z_e @ codebook^T -> quantized distance -> argmin ----
// Each block owns 128 rows and sweeps all K_=8192 codes (N never materialized).
// Epilogue reproduces the reference's fp32 rounding order:
//   t = fl(P - fl(2*dot));  d = fl(t + c);  argmin with first-index tie-break.
__global__ __launch_bounds__(256) void dist_argmin_kernel(
    const float* __restrict__ cb, float* __restrict__ out_idx_f, int write_idx)
{
    const int BM = 128, BN = 128, BK = 8;
    __shared__ float As[BK][BM];
    __shared__ float Bs[BK][BN];

    int bm = blockIdx.x * BM;
    int tid = threadIdx.x;
    int tx = tid & 15, ty = tid >> 4;
    int lrow = tid >> 1;
    int lcol = (tid & 1) * 4;

    float bestv[8];
    int   besti[8];
    float Prow[8];
    #pragma unroll
    for (int i = 0; i < 8; i++) {
        bestv[i] = FLT_MAX;
        besti[i] = 0;
        Prow[i]  = g_P[bm + ty * 8 + i];
    }

    const float* Aptr = g_ze + (size_t)(bm + lrow) * L_ + lcol;

    for (int n0 = 0; n0 < K_; n0 += BN) {
        const float* Bptr = cb + (size_t)(n0 + lrow) * L_ + lcol;
        float acc[8][8];
        #pragma unroll
        for (int i = 0; i < 8; i++)
            #pragma unroll
            for (int j = 0; j < 8; j++) acc[i][j] = 0.0f;

        for (int k0 = 0; k0 < L_; k0 += BK) {
            float4 av = *(const float4*)(Aptr + k0);
            float4 bv = *(const float4*)(Bptr + k0);
            As[lcol + 0][lrow] = av.x; As[lcol + 1][lrow] = av.y;
            As[lcol + 2][lrow] = av.z; As[lcol + 3][lrow] = av.w;
            Bs[lcol + 0][lrow] = bv.x; Bs[lcol + 1][lrow] = bv.y;
            Bs[lcol + 2][lrow] = bv.z; Bs[lcol + 3][lrow] = bv.w;
            __syncthreads();
            #pragma unroll
            for (int kk = 0; kk < BK; kk++) {
                float ar[8], br[8];
                #pragma unroll
                for (int i = 0; i < 8; i++) ar[i] = As[kk][ty * 8 + i];
                #pragma unroll
                for (int j = 0; j < 8; j++) br[j] = Bs[kk][tx * 8 + j];
                #pragma unroll
                for (int i = 0; i < 8; i++)
                    #pragma unroll
                    for (int j = 0; j < 8; j++)
                        acc[i][j] = fmaf(ar[i], br[j], acc[i][j]);
            }
            __syncthreads();
        }

        float cvals[8];
        #pragma unroll
        for (int j = 0; j < 8; j++) cvals[j] = __ldg(&g_c[n0 + tx * 8 + j]);

        #pragma unroll
        for (int i = 0; i < 8; i++) {
            #pragma unroll
            for (int j = 0; j < 8; j++) {
                float t = Prow[i] - 2.0f * acc[i][j];   // fl(P - fl(2*dot))
                float d = t + cvals[j];                  // fl(t + c)
                int col = n0 + tx * 8 + j;
                if (d < bestv[i]) { bestv[i] = d; besti[i] = col; }
            }
        }
    }

    // cross-thread per-row reduction with first-index tie-break
    __shared__ float sv[128][16];
    __shared__ int   si[128][16];
    #pragma unroll
    for (int i = 0; i < 8; i++) {
        sv[ty * 8 + i][tx] = bestv[i];
        si[ty * 8 + i][tx] = besti[i];
    }
    __syncthreads();
    if (tid < 128) {
        float bv = sv[tid][0];
        int   bi = si[tid][0];
        #pragma unroll
        for (int t = 1; t < 16; t++) {
            float v = sv[tid][t];
            int  ix = si[tid][t];
            if (v < bv || (v == bv && ix < bi)) { bv = v; bi = ix; }
        }
        g_idx[bm + tid] = bi;
        if (write_idx) out_idx_f[bm + tid] = (float)bi;
    }
}

// ---------------- per-row loss partial + z_q construction -------------------
__global__ void loss_zq_kernel(const float* __restrict__ cb)
{
    int row = blockIdx.x;
    const float* ze = g_ze + (size_t)row * L_;
    const float* q  = cb   + (size_t)g_idx[row] * L_;
    float* zq = g_zq + (size_t)row * L_;

    double s = 0.0;
    for (int j = threadIdx.x; j < L_; j += blockDim.x) {
        float z  = ze[j];
        float qq = q[j];
        float dlt = qq - z;            // fl(q - z)
        s += (double)dlt * (double)dlt;
        zq[j] = z + dlt;               // fl(z + fl(q - z))  (straight-through fwd)
    }
    __shared__ double sh[256];
    sh[threadIdx.x] = s;
    __syncthreads();
    for (int o = 128; o > 0; o >>= 1) {
        if (threadIdx.x < o) sh[threadIdx.x] += sh[threadIdx.x + o];
        __syncthreads();
    }
    if (threadIdx.x == 0) g_rowloss[row] = sh[0];
}

__global__ void loss_reduce_kernel(float* __restrict__ out_loss)
{
    __shared__ double sh[256];
    double s = 0.0;
    for (int r = threadIdx.x; r < B_; r += 256) s += g_rowloss[r];
    sh[threadIdx.x] = s;
    __syncthreads();
    for (int o = 128; o > 0; o >>= 1) {
        if (threadIdx.x < o) sh[threadIdx.x] += sh[threadIdx.x + o];
        __syncthreads();
    }
    if (threadIdx.x == 0) {
        float m = (float)(sh[0] / ((double)B_ * (double)L_));
        out_loss[0] = m + 0.25f * m;   // q_latent + 0.25 * e_latent (identical fwd)
    }
}

// ---------------- row softmax over O_=128 ------------------------------------
__global__ void softmax_kernel(float* __restrict__ logits)
{
    int row = blockIdx.x;
    float* p = logits + (size_t)row * O_;
    float v = p[threadIdx.x];

    __shared__ float shm[4];
    float m = v;
    #pragma unroll
    for (int o = 16; o > 0; o >>= 1) m = fmaxf(m, __shfl_xor_sync(0xffffffffu, m, o));
    if ((threadIdx.x & 31) == 0) shm[threadIdx.x >> 5] = m;
    __syncthreads();
    float mm = fmaxf(fmaxf(shm[0], shm[1]), fmaxf(shm[2], shm[3]));
    __syncthreads();

    float e = expf(v - mm);
    float s = e;
    #pragma unroll
    for (int o = 16; o > 0; o >>= 1) s += __shfl_xor_sync(0xffffffffu, s, o);
    if ((threadIdx.x & 31) == 0) shm[threadIdx.x >> 5] = s;
    __syncthreads();
    float ss = shm[0] + shm[1] + shm[2] + shm[3];
    p[threadIdx.x] = e / ss;
}

// ---------------- launch ------------------------------------------------------
extern "C" void kernel_launch(void* const* d_in, const int* in_sizes, int n_in,
                              void* d_out, int out_size)
{
    const float* x     = (const float*)d_in[0];
    const float* W_enc = (const float*)d_in[1];
    const float* b_enc = (const float*)d_in[2];
    const float* cb    = (const float*)d_in[3];
    const float* W_cls = (const float*)d_in[4];
    const float* b_cls = (const float*)d_in[5];
    float* out = (float*)d_out;

    float* out_logits = out;
    float* out_loss   = out + (size_t)B_ * O_;
    float* out_idx    = out + (size_t)B_ * O_ + 1;
    int has_loss = (out_size >= B_ * O_ + 1);
    int has_idx  = (out_size >= B_ * O_ + 1 + B_);

    void *p_ze, *p_zq;
    cudaGetSymbolAddress(&p_ze, g_ze);
    cudaGetSymbolAddress(&p_zq, g_zq);
    void *p_P, *p_c;
    cudaGetSymbolAddress(&p_P, g_P);
    cudaGetSymbolAddress(&p_c, g_c);
    float* ze = (float*)p_ze;
    float* zq = (float*)p_zq;
    float* Pv = (float*)p_P;
    float* cv = (float*)p_c;

    // 1) codebook row norms
    rowsumsq_kernel<<<K_ / 8, 256>>>(cb, cv, K_, L_);

    // 2) z_e = x @ W_enc^T + b_enc
    {
        dim3 grid(L_ / 128, B_ / 128);
        sgemm_nt_bias<<<grid, 256>>>(x, W_enc, b_enc, ze, B_, L_, TD_);
    }

    // 3) row norms of z_e
    rowsumsq_kernel<<<B_ / 8, 256>>>(ze, Pv, B_, L_);

    // 4) fused distance + argmin (codes never materialized)
    dist_argmin_kernel<<<B_ / 128, 256>>>(cb, out_idx, has_idx);

    // 5) per-row loss + z_q
    loss_zq_kernel<<<B_, 256>>>(cb);

    // 6) deterministic loss reduce -> vq_loss
    if (has_loss) loss_reduce_kernel<<<1, 256>>>(out_loss);

    // 7) pre-logits = z_q @ W_cls^T + b_cls
    {
        dim3 grid(O_ / 128, B_ / 128);
        sgemm_nt_bias<<<grid, 256>>>(zq, W_cls, b_cls, out_logits, B_, O_, L_);
    }

    // 8) row softmax
    softmax_kernel<<<B_, 128>>>(out_logits);
}